// round 1
// baseline (speedup 1.0000x reference)
#include <cuda_runtime.h>
#include <cuda_fp16.h>
#include <mma.h>
#include <cstdint>

using namespace nvcuda;

// ---------------- problem constants ----------------
#define Bc 4
#define Lc 4096
#define DMc 2048
#define Hc 32
#define Nc 128
#define Mrows (Bc * Lc)            // 16384
#define LDP (2 * Nc + Hc)          // 288

// ---------------- scratch (device globals; allocation-free) ----------------
__device__ __half g_xh[(size_t)Mrows * DMc];
__device__ __half g_Wxh[(size_t)DMc * LDP];
__device__ __half g_Wgh[(size_t)DMc * DMc];
__device__ __half g_Woh[(size_t)DMc * DMc];
__device__ float  g_P[(size_t)Mrows * LDP];
__device__ __half g_gate[(size_t)Mrows * DMc];
__device__ float  g_Y[(size_t)Mrows * Hc];
__device__ __half g_yf[(size_t)Mrows * DMc];

// ---------------- fp32 -> fp16 convert (half2 vectorized) ----------------
__global__ void f32_to_f16_kernel(const float* __restrict__ in,
                                  __half* __restrict__ out, int n2) {
    int i = blockIdx.x * blockDim.x + threadIdx.x;
    if (i < n2) {
        float2 v = reinterpret_cast<const float2*>(in)[i];
        reinterpret_cast<__half2*>(out)[i] = __floats2half2_rn(v.x, v.y);
    }
}

// ---------------- cp.async helpers ----------------
__device__ __forceinline__ void cp_async16(void* smem, const void* gmem, int src_size) {
    unsigned s = (unsigned)__cvta_generic_to_shared(smem);
    asm volatile("cp.async.cg.shared.global [%0], [%1], 16, %2;\n"
                 :: "r"(s), "l"(gmem), "r"(src_size));
}
__device__ __forceinline__ void cp_commit() {
    asm volatile("cp.async.commit_group;\n");
}
template <int NWAIT>
__device__ __forceinline__ void cp_wait() {
    asm volatile("cp.async.wait_group %0;\n" :: "n"(NWAIT));
}

// ---------------- fp16 GEMM: C[M,N] = A[M,K] @ B[K,N], fp32 accum ----------------
// EPI 0: store float to Cf
// EPI 1: v += bias[col]; store half(sigmoid(v)) to Ch
#define BM 128
#define BN 128
#define BKg 32

template <int EPI>
__global__ void __launch_bounds__(256)
gemm_f16_kernel(const __half* __restrict__ Ag, const __half* __restrict__ Bg,
                float* __restrict__ Cf, __half* __restrict__ Ch,
                const float* __restrict__ bias, int M, int N, int K) {
    __shared__ __align__(16) __half As[2][BM][BKg + 8];
    __shared__ __align__(16) __half Bs[2][BKg][BN + 8];
    __shared__ __align__(16) float  stage[8][16][20];

    const int m0 = blockIdx.y * BM;
    const int n0 = blockIdx.x * BN;
    const int tid = threadIdx.x;
    const int warpId = tid >> 5;
    const int lane = tid & 31;

    wmma::fragment<wmma::accumulator, 16, 16, 16, float> acc[2][4];
#pragma unroll
    for (int i = 0; i < 2; i++)
#pragma unroll
        for (int j = 0; j < 4; j++) wmma::fill_fragment(acc[i][j], 0.f);

    const int row0 = (warpId & 3) * 32;
    const int col0 = (warpId >> 2) * 64;

    auto loadA = [&](int buf, int k0) {
#pragma unroll
        for (int j = 0; j < 2; ++j) {
            int c = tid + 256 * j;     // 0..511
            int r = c >> 2, v = c & 3; // 128 rows x 4 vec16
            cp_async16(&As[buf][r][v * 8],
                       Ag + (size_t)(m0 + r) * K + k0 + v * 8, 16);
        }
    };
    auto loadB = [&](int buf, int k0) {
#pragma unroll
        for (int j = 0; j < 2; ++j) {
            int c = tid + 256 * j;       // 0..511
            int r = c >> 4, v = c & 15;  // 32 rows x 16 vec16
            int col = n0 + v * 8;
            bool ok = (col < N);
            const __half* src = Bg + (size_t)(k0 + r) * N + (ok ? col : 0);
            cp_async16(&Bs[buf][r][v * 8], src, ok ? 16 : 0);
        }
    };

    const int KT = K / BKg;
    loadA(0, 0); loadB(0, 0); cp_commit();

    for (int kt = 0; kt < KT; ++kt) {
        const int buf = kt & 1;
        if (kt + 1 < KT) {
            loadA(buf ^ 1, (kt + 1) * BKg);
            loadB(buf ^ 1, (kt + 1) * BKg);
            cp_commit();
            cp_wait<1>();
        } else {
            cp_wait<0>();
        }
        __syncthreads();

#pragma unroll
        for (int kk = 0; kk < BKg; kk += 16) {
            wmma::fragment<wmma::matrix_a, 16, 16, 16, __half, wmma::row_major> afr[2];
            wmma::fragment<wmma::matrix_b, 16, 16, 16, __half, wmma::row_major> bfr[4];
            wmma::load_matrix_sync(afr[0], &As[buf][row0][kk], BKg + 8);
            wmma::load_matrix_sync(afr[1], &As[buf][row0 + 16][kk], BKg + 8);
#pragma unroll
            for (int j = 0; j < 4; j++)
                wmma::load_matrix_sync(bfr[j], &Bs[buf][kk][col0 + 16 * j], BN + 8);
#pragma unroll
            for (int i = 0; i < 2; i++)
#pragma unroll
                for (int j = 0; j < 4; j++)
                    wmma::mma_sync(acc[i][j], afr[i], bfr[j], acc[i][j]);
        }
        __syncthreads();
    }

    // epilogue through per-warp staging (handles N edge)
#pragma unroll
    for (int i = 0; i < 2; i++) {
#pragma unroll
        for (int j = 0; j < 4; j++) {
            wmma::store_matrix_sync(&stage[warpId][0][0], acc[i][j], 20,
                                    wmma::mem_row_major);
            __syncwarp();
#pragma unroll
            for (int e = 0; e < 8; ++e) {
                int idx = lane + 32 * e;   // 0..255
                int rr = idx >> 4, cc = idx & 15;
                int row = m0 + row0 + i * 16 + rr;
                int col = n0 + col0 + j * 16 + cc;
                if (col < N) {
                    float v = stage[warpId][rr][cc];
                    if (EPI == 0) {
                        Cf[(size_t)row * N + col] = v;
                    } else {
                        v += bias[col];
                        float g = 1.f / (1.f + __expf(-v));
                        Ch[(size_t)row * N + col] = __float2half(g);
                    }
                }
            }
            __syncwarp();
        }
    }
}

// ---------------- sequential scan over L ----------------
// block per (b,h), 128 threads (one per n). Chunked shared staging of P rows.
#define CHk 32

__global__ void __launch_bounds__(128)
scan_kernel(const float* __restrict__ P, const float* __restrict__ Amat,
            float* __restrict__ Y) {
    __shared__ float sP[CHk][LDP];     // 32 x 288 floats
    __shared__ float part[4][CHk];

    const int bh = blockIdx.x;
    const int b = bh >> 5;          // / Hc
    const int h = bh & 31;
    const int n = threadIdx.x;      // 0..127
    const int warp = n >> 5, lane = n & 31;

    const float Ahn = Amat[h * Nc + n];
    const float* Pb = P + (size_t)b * Lc * LDP;
    float s = 0.f;

    for (int t0 = 0; t0 < Lc; t0 += CHk) {
        // cooperative staged load: CHk contiguous rows of P
        const float4* src = reinterpret_cast<const float4*>(Pb + (size_t)t0 * LDP);
        float4* dst = reinterpret_cast<float4*>(&sP[0][0]);
#pragma unroll
        for (int i = threadIdx.x; i < CHk * (LDP / 4); i += 128) dst[i] = src[i];
        __syncthreads();

#pragma unroll 4
        for (int i = 0; i < CHk; ++i) {
            float Bn = sP[i][n];
            float Cn = sP[i][Nc + n];
            float db = sP[i][2 * Nc + h];
            float z = db + Bn;
            float d = __logf(1.f + __expf(z));     // softplus
            float a = __expf(d * Ahn);             // decay
            s = fmaf(a, s, d * d);
            float v = s * Cn;
            v += __shfl_xor_sync(0xffffffffu, v, 16);
            v += __shfl_xor_sync(0xffffffffu, v, 8);
            v += __shfl_xor_sync(0xffffffffu, v, 4);
            v += __shfl_xor_sync(0xffffffffu, v, 2);
            v += __shfl_xor_sync(0xffffffffu, v, 1);
            if (lane == 0) part[warp][i] = v;
        }
        __syncthreads();
        if (threadIdx.x < CHk) {
            float yv = part[0][threadIdx.x] + part[1][threadIdx.x] +
                       part[2][threadIdx.x] + part[3][threadIdx.x];
            Y[(size_t)(b * Lc + t0 + threadIdx.x) * Hc + h] = yv;
        }
        // next chunk's staged load waits for the compute-loop readers via the
        // __syncthreads at the top of the next iteration? No — the barrier above
        // already separates readers of sP from the next load. part[] is only
        // rewritten after the next chunk's post-load barrier.
    }
}

// ---------------- y_full assembly (half2 vectorized) ----------------
__global__ void yfull_kernel(const __half* __restrict__ xh,
                             const __half* __restrict__ gate,
                             const float* __restrict__ Y,
                             const float* __restrict__ Dp,
                             __half* __restrict__ yf) {
    int i = blockIdx.x * blockDim.x + threadIdx.x;   // over M*DM/2 half2
    if (i >= Mrows * (DMc / 2)) return;
    int m = i >> 10;         // 1024 half2 per row
    int kk = i & 1023;
    int h = kk >> 5;         // k = 2*kk; h = k/64
    float yv = __ldg(&Y[m * Hc + h]);
    float dp = __ldg(&Dp[h]);
    __half2 xv = reinterpret_cast<const __half2*>(xh)[i];
    __half2 gv = reinterpret_cast<const __half2*>(gate)[i];
    float2 xf = __half22float2(xv);
    float2 gf = __half22float2(gv);
    float r0 = (yv + xf.x * dp) * gf.x;
    float r1 = (yv + xf.y * dp) * gf.y;
    reinterpret_cast<__half2*>(yf)[i] = __floats2half2_rn(r0, r1);
}

// ---------------- launcher ----------------
extern "C" void kernel_launch(void* const* d_in, const int* in_sizes, int n_in,
                              void* d_out, int out_size) {
    const float* x   = (const float*)d_in[0];   // [B,L,DM]
    const float* Wx  = (const float*)d_in[1];   // [DM, 288]
    const float* Wg  = (const float*)d_in[2];   // [DM, DM]
    const float* bg  = (const float*)d_in[3];   // [DM]
    const float* Wo  = (const float*)d_in[4];   // [DM, DM]
    const float* Am  = (const float*)d_in[5];   // [H, N]
    const float* Dp  = (const float*)d_in[6];   // [H]
    float* out = (float*)d_out;

    __half *xh, *Wxh, *Wgh, *Woh, *gateh, *yfh;
    float *P, *Y;
    cudaGetSymbolAddress((void**)&xh,   g_xh);
    cudaGetSymbolAddress((void**)&Wxh,  g_Wxh);
    cudaGetSymbolAddress((void**)&Wgh,  g_Wgh);
    cudaGetSymbolAddress((void**)&Woh,  g_Woh);
    cudaGetSymbolAddress((void**)&P,    g_P);
    cudaGetSymbolAddress((void**)&gateh,g_gate);
    cudaGetSymbolAddress((void**)&Y,    g_Y);
    cudaGetSymbolAddress((void**)&yfh,  g_yf);

    const int T = 256;
    // converts
    {
        int n2 = Mrows * DMc / 2;      // 16,777,216
        f32_to_f16_kernel<<<(n2 + T - 1) / T, T>>>(x, xh, n2);
    }
    {
        int n2 = DMc * LDP / 2;        // 294,912
        f32_to_f16_kernel<<<(n2 + T - 1) / T, T>>>(Wx, Wxh, n2);
    }
    {
        int n2 = DMc * DMc / 2;        // 2,097,152
        f32_to_f16_kernel<<<(n2 + T - 1) / T, T>>>(Wg, Wgh, n2);
        f32_to_f16_kernel<<<(n2 + T - 1) / T, T>>>(Wo, Woh, n2);
    }

    // P = x @ Wx  (fp32 out)
    gemm_f16_kernel<0><<<dim3((LDP + BN - 1) / BN, Mrows / BM), 256>>>(
        xh, Wxh, P, nullptr, nullptr, Mrows, LDP, DMc);

    // gate = sigmoid(x @ Wg + bg)  (fp16 out)
    gemm_f16_kernel<1><<<dim3(DMc / BN, Mrows / BM), 256>>>(
        xh, Wgh, nullptr, gateh, bg, Mrows, DMc, DMc);

    // scan -> Y [M, H]
    scan_kernel<<<Bc * Hc, 128>>>(P, Am, Y);

    // y_full = (Y + x*Dp) * gate  (fp16)
    {
        int n2 = Mrows * DMc / 2;
        yfull_kernel<<<(n2 + T - 1) / T, T>>>(xh, gateh, Y, Dp, yfh);
    }

    // out = y_full @ Wo  (fp32 out)
    gemm_f16_kernel<0><<<dim3(DMc / BN, Mrows / BM), 256>>>(
        yfh, Woh, out, nullptr, nullptr, Mrows, DMc, DMc);
}

// round 3
// speedup vs baseline: 1.4441x; 1.4441x over previous
#include <cuda_runtime.h>
#include <cuda_fp16.h>
#include <mma.h>
#include <cstdint>

using namespace nvcuda;

// ---------------- problem constants ----------------
#define Bc 4
#define Lc 4096
#define DMc 2048
#define Hc 32
#define Nc 128
#define Mrows (Bc * Lc)            // 16384
#define LDP (2 * Nc + Hc)          // 288
#define SEG 8
#define LSEG (Lc / SEG)            // 512
#define CHk 32

// ---------------- scratch (device globals; allocation-free) ----------------
__device__ __half g_xh [(size_t)Mrows * DMc];
__device__ __half g_Wxh[(size_t)DMc * LDP];
__device__ __half g_Wgh[(size_t)DMc * DMc];
__device__ __half g_Woh[(size_t)DMc * DMc];
__device__ float  g_P  [(size_t)Mrows * LDP];
__device__ __half g_gate[(size_t)Mrows * DMc];
__device__ float  g_Y  [(size_t)Mrows * Hc];
__device__ __half g_yf [(size_t)Mrows * DMc];
__device__ float  g_segstate[Bc * Hc * SEG * Nc];
__device__ float  g_segdecay[Bc * Hc * SEG * Nc];
__device__ float  g_seghin  [Bc * Hc * SEG * Nc];

// ---------------- cp.async helpers ----------------
__device__ __forceinline__ void cp16(void* smem, const void* gmem, int sz) {
    unsigned s = (unsigned)__cvta_generic_to_shared(smem);
    asm volatile("cp.async.cg.shared.global [%0], [%1], 16, %2;\n"
                 :: "r"(s), "l"(gmem), "r"(sz));
}
__device__ __forceinline__ void cp_commit() {
    asm volatile("cp.async.commit_group;\n");
}
template <int NWAIT>
__device__ __forceinline__ void cp_wait() {
    asm volatile("cp.async.wait_group %0;\n" :: "n"(NWAIT));
}

// ---------------- converts ----------------
__global__ void f32_to_f16_v4(const float* __restrict__ in,
                              __half* __restrict__ out, int n4) {
    int i = blockIdx.x * blockDim.x + threadIdx.x;
    if (i < n4) {
        float4 v = reinterpret_cast<const float4*>(in)[i];
        __half2 a = __floats2half2_rn(v.x, v.y);
        __half2 b = __floats2half2_rn(v.z, v.w);
        uint2 r;
        r.x = *reinterpret_cast<uint32_t*>(&a);
        r.y = *reinterpret_cast<uint32_t*>(&b);
        reinterpret_cast<uint2*>(out)[i] = r;
    }
}

// ---------------- wmma fp16 GEMM ----------------
// C[M,N] = A[M,K] @ B[K,N]; fp32 accum. 128x128 tile, BK=64, 3 stages.
#define BM 128
#define BN 128
#define BKg 64
#define SKA 72      // A smem row stride (halves): 144B, 16B-aligned
#define SKB 136     // B smem row stride (halves): 272B, 16B-aligned
#define A_STG_H (BM * SKA)                 // halves per A stage
#define B_STG_H (BKg * SKB)                // halves per B stage
#define A_BYTES (3 * A_STG_H * 2)          // 55296
#define GEMM_DSMEM (A_BYTES + 3 * B_STG_H * 2)   // 107520

template <int EPI>
__global__ void __launch_bounds__(256)
gemm_wmma(const __half* __restrict__ Ag, const __half* __restrict__ Bg,
          float* __restrict__ Cf, __half* __restrict__ Ch,
          const float* __restrict__ bias, int M, int N, int K) {
    extern __shared__ __align__(16) char dsm[];
    __half* Asm = reinterpret_cast<__half*>(dsm);
    __half* Bsm = reinterpret_cast<__half*>(dsm + A_BYTES);

    const int m0 = blockIdx.y * BM;
    const int n0 = blockIdx.x * BN;
    const int tid = threadIdx.x;
    const int warpId = tid >> 5;
    const int lane = tid & 31;
    const int KT = K / BKg;

    wmma::fragment<wmma::accumulator, 16, 16, 16, float> acc[2][4];
#pragma unroll
    for (int i = 0; i < 2; i++)
#pragma unroll
        for (int j = 0; j < 4; j++) wmma::fill_fragment(acc[i][j], 0.f);

    const int row0 = (warpId & 3) * 32;
    const int col0 = (warpId >> 2) * 64;

    auto load_stage = [&](int slot, int kt) {
        __half* As = Asm + slot * A_STG_H;
        __half* Bs = Bsm + slot * B_STG_H;
        const int k0 = kt * BKg;
#pragma unroll
        for (int j = 0; j < 4; ++j) {
            int idx = tid + 256 * j;        // 0..1023
            int r = idx >> 3, v = idx & 7;  // 128 rows x 8 vec16
            cp16(As + r * SKA + v * 8,
                 Ag + (size_t)(m0 + r) * K + k0 + v * 8, 16);
        }
#pragma unroll
        for (int j = 0; j < 4; ++j) {
            int idx = tid + 256 * j;          // 0..1023
            int r = idx >> 4, v = idx & 15;   // 64 rows x 16 vec16
            int col = n0 + v * 8;
            bool ok = (col < N);
            cp16(Bs + r * SKB + v * 8,
                 Bg + (size_t)(k0 + r) * N + (ok ? col : 0), ok ? 16 : 0);
        }
        cp_commit();
    };

    load_stage(0, 0);
    load_stage(1, 1);

    for (int kt = 0; kt < KT; ++kt) {
        // refill slot (kt-1)%3 with stage kt+2 (safe: trailing barrier of kt-1)
        if (kt + 2 < KT) load_stage((kt + 2) % 3, kt + 2);
        else cp_commit();                        // keep group count uniform
        cp_wait<2>();                            // stage kt complete
        __syncthreads();

        const int slot = kt % 3;
        const __half* As = Asm + slot * A_STG_H;
        const __half* Bs = Bsm + slot * B_STG_H;
#pragma unroll
        for (int kk = 0; kk < BKg; kk += 16) {
            wmma::fragment<wmma::matrix_a, 16, 16, 16, __half, wmma::row_major> afr[2];
            wmma::fragment<wmma::matrix_b, 16, 16, 16, __half, wmma::row_major> bfr[4];
            wmma::load_matrix_sync(afr[0], As + row0 * SKA + kk, SKA);
            wmma::load_matrix_sync(afr[1], As + (row0 + 16) * SKA + kk, SKA);
#pragma unroll
            for (int j = 0; j < 4; j++)
                wmma::load_matrix_sync(bfr[j], Bs + kk * SKB + col0 + 16 * j, SKB);
#pragma unroll
            for (int i = 0; i < 2; i++)
#pragma unroll
                for (int j = 0; j < 4; j++)
                    wmma::mma_sync(acc[i][j], afr[i], bfr[j], acc[i][j]);
        }
        __syncthreads();
    }

    // ---- epilogue via per-warp smem staging (handles N edge) ----
    float* stage = reinterpret_cast<float*>(dsm) + warpId * (16 * 20);
#pragma unroll
    for (int i = 0; i < 2; i++) {
#pragma unroll
        for (int j = 0; j < 4; j++) {
            wmma::store_matrix_sync(stage, acc[i][j], 20, wmma::mem_row_major);
            __syncwarp();
#pragma unroll
            for (int e = 0; e < 8; ++e) {
                int idx = lane + 32 * e;   // 0..255
                int rr = idx >> 4, cc = idx & 15;
                int row = m0 + row0 + i * 16 + rr;
                int col = n0 + col0 + j * 16 + cc;
                if (col < N) {
                    float v = stage[rr * 20 + cc];
                    if (EPI == 0) {
                        Cf[(size_t)row * N + col] = v;
                    } else {
                        v += bias[col];
                        float g = 1.f / (1.f + __expf(-v));
                        Ch[(size_t)row * N + col] = __float2half(g);
                    }
                }
            }
            __syncwarp();
        }
    }
}

// ---------------- segmented scan ----------------
// pass 1: per-(b,h,seg): state with h_in=0 and decay = exp(A * sum d)
__global__ void __launch_bounds__(128)
scan_pass1(const float* __restrict__ P, const float* __restrict__ Amat,
           float* __restrict__ segstate, float* __restrict__ segdecay) {
    __shared__ float sP[CHk][LDP];
    const int blk = blockIdx.x;              // ((b*H + h)*SEG + seg)
    const int seg = blk & (SEG - 1);
    const int bh = blk >> 3;
    const int b = bh >> 5, h = bh & 31;
    const int n = threadIdx.x;
    const float Ahn = Amat[h * Nc + n];
    const float* Pb = P + ((size_t)b * Lc + seg * LSEG) * LDP;
    float s = 0.f, sumd = 0.f;

    for (int t0 = 0; t0 < LSEG; t0 += CHk) {
        const float4* src = reinterpret_cast<const float4*>(Pb + (size_t)t0 * LDP);
        float4* dst = reinterpret_cast<float4*>(&sP[0][0]);
        for (int i = threadIdx.x; i < CHk * (LDP / 4); i += 128) dst[i] = src[i];
        __syncthreads();
#pragma unroll 4
        for (int i = 0; i < CHk; ++i) {
            float z = sP[i][2 * Nc + h] + sP[i][n];
            float d = __logf(1.f + __expf(z));
            float a = __expf(d * Ahn);
            s = fmaf(a, s, d * d);
            sumd += d;
        }
        __syncthreads();
    }
    segstate[blk * Nc + n] = s;
    segdecay[blk * Nc + n] = __expf(Ahn * sumd);
}

// pass 2: sequential combine across segments (tiny)
__global__ void scan_pass2(const float* __restrict__ state,
                           const float* __restrict__ decay,
                           float* __restrict__ hin) {
    int i = blockIdx.x * blockDim.x + threadIdx.x;   // Bc*Hc*Nc
    if (i >= Bc * Hc * Nc) return;
    int bh = i >> 7, n = i & 127;
    float h = 0.f;
#pragma unroll
    for (int s = 0; s < SEG; s++) {
        int idx = (bh * SEG + s) * Nc + n;
        hin[idx] = h;
        h = decay[idx] * h + state[idx];
    }
}

// pass 3: re-run with correct h_in, emit y
__global__ void __launch_bounds__(128)
scan_pass3(const float* __restrict__ P, const float* __restrict__ Amat,
           const float* __restrict__ hin, float* __restrict__ Y) {
    __shared__ float sP[CHk][LDP];
    __shared__ float part[4][CHk];
    const int blk = blockIdx.x;
    const int seg = blk & (SEG - 1);
    const int bh = blk >> 3;
    const int b = bh >> 5, h = bh & 31;
    const int n = threadIdx.x;
    const int warp = n >> 5, lane = n & 31;
    const float Ahn = Amat[h * Nc + n];
    const float* Pb = P + ((size_t)b * Lc + seg * LSEG) * LDP;
    float s = hin[blk * Nc + n];

    for (int t0 = 0; t0 < LSEG; t0 += CHk) {
        const float4* src = reinterpret_cast<const float4*>(Pb + (size_t)t0 * LDP);
        float4* dst = reinterpret_cast<float4*>(&sP[0][0]);
        for (int i = threadIdx.x; i < CHk * (LDP / 4); i += 128) dst[i] = src[i];
        __syncthreads();
#pragma unroll 4
        for (int i = 0; i < CHk; ++i) {
            float Bn = sP[i][n];
            float Cn = sP[i][Nc + n];
            float db = sP[i][2 * Nc + h];
            float z = db + Bn;
            float d = __logf(1.f + __expf(z));
            float a = __expf(d * Ahn);
            s = fmaf(a, s, d * d);
            float v = s * Cn;
            v += __shfl_xor_sync(0xffffffffu, v, 16);
            v += __shfl_xor_sync(0xffffffffu, v, 8);
            v += __shfl_xor_sync(0xffffffffu, v, 4);
            v += __shfl_xor_sync(0xffffffffu, v, 2);
            v += __shfl_xor_sync(0xffffffffu, v, 1);
            if (lane == 0) part[warp][i] = v;
        }
        __syncthreads();
        if (threadIdx.x < CHk) {
            float yv = part[0][threadIdx.x] + part[1][threadIdx.x] +
                       part[2][threadIdx.x] + part[3][threadIdx.x];
            Y[(size_t)(b * Lc + seg * LSEG + t0 + threadIdx.x) * Hc + h] = yv;
        }
        __syncthreads();
    }
}

// ---------------- y_full assembly ----------------
__global__ void yfull_kernel(const __half* __restrict__ xh,
                             const __half* __restrict__ gate,
                             const float* __restrict__ Y,
                             const float* __restrict__ Dp,
                             __half* __restrict__ yf) {
    int i = blockIdx.x * blockDim.x + threadIdx.x;   // over M*DM/2 half2
    if (i >= Mrows * (DMc / 2)) return;
    int m = i >> 10;
    int kk = i & 1023;
    int h = kk >> 5;
    float yv = __ldg(&Y[m * Hc + h]);
    float dp = __ldg(&Dp[h]);
    __half2 xv = reinterpret_cast<const __half2*>(xh)[i];
    __half2 gv = reinterpret_cast<const __half2*>(gate)[i];
    float2 xf = __half22float2(xv);
    float2 gf = __half22float2(gv);
    float r0 = (yv + xf.x * dp) * gf.x;
    float r1 = (yv + xf.y * dp) * gf.y;
    reinterpret_cast<__half2*>(yf)[i] = __floats2half2_rn(r0, r1);
}

// ---------------- launcher ----------------
extern "C" void kernel_launch(void* const* d_in, const int* in_sizes, int n_in,
                              void* d_out, int out_size) {
    const float* x  = (const float*)d_in[0];
    const float* Wx = (const float*)d_in[1];
    const float* Wg = (const float*)d_in[2];
    const float* bg = (const float*)d_in[3];
    const float* Wo = (const float*)d_in[4];
    const float* Am = (const float*)d_in[5];
    const float* Dp = (const float*)d_in[6];
    float* out = (float*)d_out;

    __half *xh, *Wxh, *Wgh, *Woh, *gateh, *yfh;
    float *P, *Y, *sst, *sdc, *shn;
    cudaGetSymbolAddress((void**)&xh,  g_xh);
    cudaGetSymbolAddress((void**)&Wxh, g_Wxh);
    cudaGetSymbolAddress((void**)&Wgh, g_Wgh);
    cudaGetSymbolAddress((void**)&Woh, g_Woh);
    cudaGetSymbolAddress((void**)&P,   g_P);
    cudaGetSymbolAddress((void**)&gateh, g_gate);
    cudaGetSymbolAddress((void**)&Y,   g_Y);
    cudaGetSymbolAddress((void**)&yfh, g_yf);
    cudaGetSymbolAddress((void**)&sst, g_segstate);
    cudaGetSymbolAddress((void**)&sdc, g_segdecay);
    cudaGetSymbolAddress((void**)&shn, g_seghin);

    cudaFuncSetAttribute(gemm_wmma<0>, cudaFuncAttributeMaxDynamicSharedMemorySize, GEMM_DSMEM);
    cudaFuncSetAttribute(gemm_wmma<1>, cudaFuncAttributeMaxDynamicSharedMemorySize, GEMM_DSMEM);

    const int T = 256;
    // converts: x, Wx, Wg, Wo  (launches 1-4)
    {
        int n4 = Mrows * DMc / 4;
        f32_to_f16_v4<<<(n4 + T - 1) / T, T>>>(x, xh, n4);
    }
    {
        int n4 = DMc * LDP / 4;
        f32_to_f16_v4<<<(n4 + T - 1) / T, T>>>(Wx, Wxh, n4);
    }
    {
        int n4 = DMc * DMc / 4;
        f32_to_f16_v4<<<(n4 + T - 1) / T, T>>>(Wg, Wgh, n4);
        f32_to_f16_v4<<<(n4 + T - 1) / T, T>>>(Wo, Woh, n4);
    }

    // launch 5: P = x @ Wx (fp32)
    gemm_wmma<0><<<dim3((LDP + BN - 1) / BN, Mrows / BM), 256, GEMM_DSMEM>>>(
        xh, Wxh, P, nullptr, nullptr, Mrows, LDP, DMc);

    // launch 6 (ncu-captured): gate = sigmoid(x @ Wg + bg) (fp16)
    gemm_wmma<1><<<dim3(DMc / BN, Mrows / BM), 256, GEMM_DSMEM>>>(
        xh, Wgh, nullptr, gateh, bg, Mrows, DMc, DMc);

    // segmented scan
    scan_pass1<<<Bc * Hc * SEG, 128>>>(P, Am, sst, sdc);
    scan_pass2<<<(Bc * Hc * Nc + T - 1) / T, T>>>(sst, sdc, shn);
    scan_pass3<<<Bc * Hc * SEG, 128>>>(P, Am, shn, Y);

    // y_full
    {
        int n2 = Mrows * DMc / 2;
        yfull_kernel<<<(n2 + T - 1) / T, T>>>(xh, gateh, Y, Dp, yfh);
    }

    // out = y_full @ Wo (fp32)
    gemm_wmma<0><<<dim3(DMc / BN, Mrows / BM), 256, GEMM_DSMEM>>>(
        yfh, Woh, out, nullptr, nullptr, Mrows, DMc, DMc);
}